// round 7
// baseline (speedup 1.0000x reference)
#include <cuda_runtime.h>
#include <cuda_bf16.h>
#include <cstdint>

typedef unsigned long long ull;

#define TT   128
#define BB   64
#define HH   512
#define EE   256
#define VV   5000
#define NSTEP 255          /* 128 enc + 127 dec */
#define NCOLS_E 8192       /* 128*64 */
#define NCOLS_D 8128       /* 127*64 */
#define RNN_CTAS 128
#define RNN_THREADS 512
/* smem floats: w0 8192 | w1 16384 | red0 3072 | red1 3072 */
#define RED0_OFF 24576
#define RED1_OFF 27648
#define W_SMEM_FLOATS 30720
#define W_SMEM_BYTES  (W_SMEM_FLOATS * 4)

/* ---------------- device scratch (static, no allocation) ---------------- */
__device__ float g_xe[NCOLS_E][EE];
__device__ float g_xd[NCOLS_D][EE];
__device__ float g_pre_e[TT][HH][BB][4];
__device__ float g_pre_d[TT - 1][HH][BB][4];
__device__ float g_w0e[HH][HH][4];
__device__ float g_w0d[HH][HH][4];
__device__ float g_w1e[HH][2 * HH][4];
__device__ float g_w1d[HH][2 * HH][4];
__device__ float g_h0[2][HH][BB];
__device__ float g_h1[2][HH][BB];
__device__ float g_hist[NCOLS_D][HH];
__device__ unsigned g_count;
__device__ unsigned g_phase;

/* ---------------- f32x2 helpers ---------------- */
__device__ __forceinline__ void fma2(ull& acc, ull a, ull b) {
    asm("fma.rn.f32x2 %0, %1, %2, %0;" : "+l"(acc) : "l"(a), "l"(b));
}
__device__ __forceinline__ ull add2(ull a, ull b) {
    ull r; asm("add.rn.f32x2 %0, %1, %2;" : "=l"(r) : "l"(a), "l"(b));
    return r;
}
__device__ __forceinline__ ull splat2(float x) {
    ull r; unsigned u = __float_as_uint(x);
    asm("mov.b64 %0, {%1, %1};" : "=l"(r) : "r"(u));
    return r;
}
__device__ __forceinline__ float2 unpack2(ull v) {
    unsigned lo, hi;
    asm("mov.b64 {%0, %1}, %2;" : "=r"(lo), "=r"(hi) : "l"(v));
    float2 f; f.x = __uint_as_float(lo); f.y = __uint_as_float(hi);
    return f;
}
__device__ __forceinline__ float sigf(float x) { return 1.0f / (1.0f + __expf(-x)); }

/* ---------------- reset ---------------- */
__global__ void reset_kernel(float* __restrict__ out) {
    int i = blockIdx.x * blockDim.x + threadIdx.x;
    if (i < BB * VV) out[i] = 0.0f;
    if (i < HH * BB) {
        (&g_h0[0][0][0])[i] = 0.0f;
        (&g_h1[0][0][0])[i] = 0.0f;
    }
    if (i == 0) { g_count = 0u; g_phase = 0u; }
}

/* ---------------- embedding gather ---------------- */
__global__ void gather_kernel(const float* __restrict__ emb,
                              const int* __restrict__ tok,
                              int ncols, int dec) {
    int i = blockIdx.x * blockDim.x + threadIdx.x;
    if (i >= ncols * (EE / 4)) return;
    int col = i >> 6;
    int e4  = i & 63;
    float4 v = ((const float4*)emb)[(size_t)tok[col] * 64 + e4];
    float4* dst = dec ? (float4*)&g_xd[0][0] : (float4*)&g_xe[0][0];
    dst[(size_t)col * 64 + e4] = v;
}

/* ---------------- weight repack ---------------- */
__global__ void repack_kernel(const float* __restrict__ eWhh0, const float* __restrict__ dWhh0,
                              const float* __restrict__ eWih1, const float* __restrict__ eWhh1,
                              const float* __restrict__ dWih1, const float* __restrict__ dWhh1) {
    int stride = gridDim.x * blockDim.x;
    int idx = blockIdx.x * blockDim.x + threadIdx.x;
    for (int i = idx; i < HH * HH; i += stride) {
        int u = i / HH, k = i % HH;
        #pragma unroll
        for (int g = 0; g < 4; g++) {
            g_w0e[u][k][g] = eWhh0[(size_t)(g * HH + u) * HH + k];
            g_w0d[u][k][g] = dWhh0[(size_t)(g * HH + u) * HH + k];
        }
    }
    for (int i = idx; i < HH * 2 * HH; i += stride) {
        int u = i / (2 * HH), k = i % (2 * HH);
        #pragma unroll
        for (int g = 0; g < 4; g++) {
            float ve, vd;
            if (k < HH) { ve = eWih1[(size_t)(g * HH + u) * HH + k];
                          vd = dWih1[(size_t)(g * HH + u) * HH + k]; }
            else        { ve = eWhh1[(size_t)(g * HH + u) * HH + (k - HH)];
                          vd = dWhh1[(size_t)(g * HH + u) * HH + (k - HH)]; }
            g_w1e[u][k][g] = ve;
            g_w1d[u][k][g] = vd;
        }
    }
}

/* ---------------- generic 64x64 tiled fp32 GEMM, C = A(MxK) * B(NxK)^T ---------------- */
__global__ void __launch_bounds__(256) gemm_kernel(
    const float* __restrict__ A, int M, int K, int mode,
    const float* __restrict__ bias,
    const int* __restrict__ src, const float* __restrict__ vs,
    float* __restrict__ outp) {
    __shared__ float As[32][64];
    __shared__ float Bs[32][64];

    const float* B = (mode == 0) ? &g_xe[0][0] : (mode == 1) ? &g_xd[0][0] : &g_hist[0][0];

    int tid = threadIdx.x;
    int r = (tid & 15) << 2;
    int c = (tid >> 4) << 2;
    int m0 = blockIdx.y * 64;
    int n0 = blockIdx.x * 64;

    ull acc[4][2];
    #pragma unroll
    for (int i = 0; i < 4; i++) { acc[i][0] = 0ull; acc[i][1] = 0ull; }

    for (int kt = 0; kt < K; kt += 32) {
        #pragma unroll
        for (int rep = 0; rep < 2; rep++) {
            int f = tid + rep * 256;
            int m = f >> 3;
            int k4 = (f & 7) << 2;
            int gm = m0 + m;
            float4 va = make_float4(0.f, 0.f, 0.f, 0.f);
            if (gm < M) va = *(const float4*)&A[(size_t)gm * K + kt + k4];
            As[k4 + 0][m] = va.x; As[k4 + 1][m] = va.y;
            As[k4 + 2][m] = va.z; As[k4 + 3][m] = va.w;
            float4 vb = *(const float4*)&B[(size_t)(n0 + m) * K + kt + k4];
            Bs[k4 + 0][m] = vb.x; Bs[k4 + 1][m] = vb.y;
            Bs[k4 + 2][m] = vb.z; Bs[k4 + 3][m] = vb.w;
        }
        __syncthreads();
        #pragma unroll
        for (int k = 0; k < 32; k++) {
            float4 av = *(const float4*)&As[k][r];
            float4 bv = *(const float4*)&Bs[k][c];
            ull b01 = ((const ull*)&bv)[0];
            ull b23 = ((const ull*)&bv)[1];
            ull a0 = splat2(av.x), a1 = splat2(av.y), a2 = splat2(av.z), a3 = splat2(av.w);
            fma2(acc[0][0], a0, b01); fma2(acc[0][1], a0, b23);
            fma2(acc[1][0], a1, b01); fma2(acc[1][1], a1, b23);
            fma2(acc[2][0], a2, b01); fma2(acc[2][1], a2, b23);
            fma2(acc[3][0], a3, b01); fma2(acc[3][1], a3, b23);
        }
        __syncthreads();
    }

    #pragma unroll
    for (int i = 0; i < 4; i++) {
        int m = m0 + r + i;
        if (m >= M) continue;
        float bval = bias[m];
        float2 v01 = unpack2(acc[i][0]);
        float2 v23 = unpack2(acc[i][1]);
        float vals[4] = { v01.x + bval, v01.y + bval, v23.x + bval, v23.y + bval };
        #pragma unroll
        for (int j = 0; j < 4; j++) {
            int n = n0 + c + j;
            if (mode == 2) {
                int s0 = src[n], s1 = src[n + 64];
                float sim = fminf(vs[(size_t)s0 * VV + m], vs[(size_t)s1 * VV + m]);
                float md = fminf(sim, 20.0f);
                float mult = (m == 3 || m == 4 || m == VV - 1) ? 1.0f
                                                               : (md * md - 20.0f * md + 1.0f);
                outp[(size_t)(n + 64) * VV + m] = vals[j] * mult;
            } else {
                int t = n >> 6, b = n & 63;
                int uu = m & 511, g = m >> 9;
                float* dst = (mode == 0) ? &g_pre_e[0][0][0][0] : &g_pre_d[0][0][0][0];
                dst[(((size_t)t * HH + uu) * BB + b) * 4 + g] = vals[j];
            }
        }
    }
}

/* ---------------- grid barrier ---------------- */
__device__ __forceinline__ void grid_barrier(unsigned nctas, unsigned& local_phase) {
    __syncthreads();
    if (threadIdx.x == 0) {
        unsigned target = local_phase + 1u;
        __threadfence();
        unsigned old = atomicAdd(&g_count, 1u);
        if (old == nctas - 1u) {
            g_count = 0u;
            __threadfence();
            atomicExch(&g_phase, target);
        } else {
            while (*(volatile unsigned*)&g_phase < target) { }
            __threadfence();
        }
    }
    local_phase++;
    __syncthreads();
}

/* ---------------- software-pipelined GEMV over cnt k values (depth 8) ---------------- */
__device__ __forceinline__ void gemv_pass(const float* __restrict__ hbase,
                                          const ulonglong2* __restrict__ wbase,
                                          int cnt,
                                          ull& aif0, ull& ago0, ull& aif1, ull& ago1) {
    float2 bufA[8], bufB[8];
    #pragma unroll
    for (int i = 0; i < 8; i++)
        bufA[i] = *(const float2*)(hbase + (size_t)i * BB);

    #pragma unroll 1
    for (int k = 0; k < cnt; k += 16) {
        #pragma unroll
        for (int i = 0; i < 8; i++)
            bufB[i] = *(const float2*)(hbase + (size_t)(k + 8 + i) * BB);
        #pragma unroll
        for (int i = 0; i < 8; i++) {
            ulonglong2 w = wbase[k + i];
            ull ha = splat2(bufA[i].x), hb = splat2(bufA[i].y);
            fma2(aif0, ha, w.x); fma2(ago0, ha, w.y);
            fma2(aif1, hb, w.x); fma2(ago1, hb, w.y);
        }
        int kn = (k + 16 < cnt) ? (k + 16) : 0;   /* harmless wrap prefetch */
        #pragma unroll
        for (int i = 0; i < 8; i++)
            bufA[i] = *(const float2*)(hbase + (size_t)(kn + i) * BB);
        #pragma unroll
        for (int i = 0; i < 8; i++) {
            ulonglong2 w = wbase[k + 8 + i];
            ull ha = splat2(bufB[i].x), hb = splat2(bufB[i].y);
            fma2(aif0, ha, w.x); fma2(ago0, ha, w.y);
            fma2(aif1, hb, w.x); fma2(ago1, hb, w.y);
        }
    }
}

/* ---------------- persistent LSTM recurrence: 512 thr, 4 warps/SMSP ----------------
   16 warps: grp = warp>>2 in {0..3}, usub = warp&3 -> unit u, lanes -> batch pairs.
   Layer 0: grp g takes k in [g*128, g*128+128)            -> reduce in red0.
   Layer 1: grp0/1 split h0new pass, grp2/3 split h1old    -> reduce in red1.
   Group 0 performs reductions + LSTM epilogues.                              */
__global__ void __launch_bounds__(RNN_THREADS, 1) rnn_kernel(const float* __restrict__ eb1,
                                                             const float* __restrict__ db1) {
    extern __shared__ float s_w[];
    const int tid  = threadIdx.x;
    const int lane = tid & 31;
    const int warp = tid >> 5;
    const int grp  = warp >> 2;             /* 0..3 */
    const int usub = warp & 3;
    const int u = blockIdx.x * 4 + usub;
    const int b0 = lane * 2;
    const int slot = tid & 127;             /* (usub, lane) id, same across groups */
    const unsigned nctas = gridDim.x;
    unsigned phase = 0;

    ull* red0 = (ull*)&s_w[RED0_OFF];       /* [3][128][4] ull */
    ull* red1 = (ull*)&s_w[RED1_OFF];

    float2 c0 = make_float2(0.f, 0.f);
    float2 c1 = make_float2(0.f, 0.f);

    float be[4], bd[4];
    #pragma unroll
    for (int g = 0; g < 4; g++) { be[g] = eb1[g * HH + u]; bd[g] = db1[g * HH + u]; }

    const ulonglong2* w0s = (const ulonglong2*)&s_w[usub * 2048];          /* [512]  */
    const ulonglong2* w1s = (const ulonglong2*)&s_w[8192 + usub * 4096];   /* [1024] */

    for (int t = 0; t < NSTEP; t++) {
        const bool enc = (t < TT);

        if (t == 0 || t == TT) {
            const float4* src0 = (const float4*)(enc ? &g_w0e[blockIdx.x * 4][0][0]
                                                     : &g_w0d[blockIdx.x * 4][0][0]);
            const float4* src1 = (const float4*)(enc ? &g_w1e[blockIdx.x * 4][0][0]
                                                     : &g_w1d[blockIdx.x * 4][0][0]);
            float4* d0 = (float4*)s_w;
            float4* d1 = (float4*)(s_w + 8192);
            for (int i = tid; i < 2048; i += RNN_THREADS) d0[i] = src0[i];
            for (int i = tid; i < 4096; i += RNN_THREADS) d1[i] = src1[i];
            __syncthreads();
        }

        /* ---- layer 0: gates = pre[t] + Whh0 @ h0old, k split 4 ways ---- */
        const float* h0old = &g_h0[t & 1][0][0] + b0;
        {
            ull aif0 = 0ull, ago0 = 0ull, aif1 = 0ull, ago1 = 0ull;
            gemv_pass(h0old + grp * 128 * BB, w0s + grp * 128, 128,
                      aif0, ago0, aif1, ago1);
            if (grp != 0) {
                ull* r = red0 + ((grp - 1) * 128 + slot) * 4;
                r[0] = aif0; r[1] = ago0; r[2] = aif1; r[3] = ago1;
            }
            __syncthreads();
            if (grp == 0) {
                #pragma unroll
                for (int g = 0; g < 3; g++) {
                    ull* r = red0 + (g * 128 + slot) * 4;
                    aif0 = add2(aif0, r[0]); ago0 = add2(ago0, r[1]);
                    aif1 = add2(aif1, r[2]); ago1 = add2(ago1, r[3]);
                }
                const float4* pre4 = enc ? (const float4*)&g_pre_e[t][u][0][0]
                                         : (const float4*)&g_pre_d[t - TT][u][0][0];
                float4 p0 = pre4[b0];
                float4 p1 = pre4[b0 + 1];
                float2 if0 = unpack2(aif0), go0 = unpack2(ago0);
                float2 if1 = unpack2(aif1), go1 = unpack2(ago1);
                float zi0 = if0.x + p0.x, zf0 = if0.y + p0.y;
                float zg0 = go0.x + p0.z, zo0 = go0.y + p0.w;
                float zi1 = if1.x + p1.x, zf1 = if1.y + p1.y;
                float zg1 = go1.x + p1.z, zo1 = go1.y + p1.w;
                c0.x = sigf(zf0) * c0.x + sigf(zi0) * tanhf(zg0);
                c0.y = sigf(zf1) * c0.y + sigf(zi1) * tanhf(zg1);
                float2 h0n;
                h0n.x = sigf(zo0) * tanhf(c0.x);
                h0n.y = sigf(zo1) * tanhf(c0.y);
                *(float2*)(&g_h0[(t + 1) & 1][0][0] + (size_t)u * BB + b0) = h0n;
            }
        }

        grid_barrier(nctas, phase);

        /* ---- layer 1: grp0/1 do Wih1@h0new halves, grp2/3 do Whh1@h1old halves ---- */
        {
            ull bif0 = 0ull, bgo0 = 0ull, bif1 = 0ull, bgo1 = 0ull;
            const float* hb;
            const ulonglong2* wb;
            if (grp < 2) {
                hb = &g_h0[(t + 1) & 1][0][0] + b0 + (grp & 1) * 256 * BB;
                wb = w1s + (grp & 1) * 256;
            } else {
                hb = &g_h1[t & 1][0][0] + b0 + (grp & 1) * 256 * BB;
                wb = w1s + HH + (grp & 1) * 256;
            }
            gemv_pass(hb, wb, 256, bif0, bgo0, bif1, bgo1);
            if (grp != 0) {
                ull* r = red1 + ((grp - 1) * 128 + slot) * 4;
                r[0] = bif0; r[1] = bgo0; r[2] = bif1; r[3] = bgo1;
            }
            __syncthreads();
            if (grp == 0) {
                #pragma unroll
                for (int g = 0; g < 3; g++) {
                    ull* r = red1 + (g * 128 + slot) * 4;
                    bif0 = add2(bif0, r[0]); bgo0 = add2(bgo0, r[1]);
                    bif1 = add2(bif1, r[2]); bgo1 = add2(bgo1, r[3]);
                }
                float bi = enc ? be[0] : bd[0];
                float bf = enc ? be[1] : bd[1];
                float bg = enc ? be[2] : bd[2];
                float bo = enc ? be[3] : bd[3];
                float2 if0 = unpack2(bif0), go0 = unpack2(bgo0);
                float2 if1 = unpack2(bif1), go1 = unpack2(bgo1);
                float zi0 = if0.x + bi, zf0 = if0.y + bf;
                float zg0 = go0.x + bg, zo0 = go0.y + bo;
                float zi1 = if1.x + bi, zf1 = if1.y + bf;
                float zg1 = go1.x + bg, zo1 = go1.y + bo;
                c1.x = sigf(zf0) * c1.x + sigf(zi0) * tanhf(zg0);
                c1.y = sigf(zf1) * c1.y + sigf(zi1) * tanhf(zg1);
                float2 h1n;
                h1n.x = sigf(zo0) * tanhf(c1.x);
                h1n.y = sigf(zo1) * tanhf(c1.y);
                *(float2*)(&g_h1[(t + 1) & 1][0][0] + (size_t)u * BB + b0) = h1n;
                if (!enc) {
                    int col = (t - TT) * BB + b0;
                    g_hist[col][u] = h1n.x;
                    g_hist[col + 1][u] = h1n.y;
                }
            }
        }
        /* layer-1(t) writes are protected by the grid barrier inside step t+1 */
    }
}

/* ---------------- launch ---------------- */
extern "C" void kernel_launch(void* const* d_in, const int* in_sizes, int n_in,
                              void* d_out, int out_size) {
    const void* in[32];
    int j = 0;
    for (int k = 0; k < n_in && j < 32; k++) {
        if (in_sizes[k] == 1) continue;       /* skip scalar src_lens/trg_lens */
        in[j++] = d_in[k];
    }
    const int*   src   = (const int*)in[0];
    const int*   trg   = (const int*)in[1];
    const float* vs    = (const float*)in[2];
    const float* embE  = (const float*)in[3];
    const float* embD  = (const float*)in[4];
    const float* eWih0 = (const float*)in[5];
    const float* eWhh0 = (const float*)in[6];
    const float* eb0   = (const float*)in[7];
    const float* eWih1 = (const float*)in[8];
    const float* eWhh1 = (const float*)in[9];
    const float* eb1   = (const float*)in[10];
    const float* dWih0 = (const float*)in[11];
    const float* dWhh0 = (const float*)in[12];
    const float* db0   = (const float*)in[13];
    const float* dWih1 = (const float*)in[14];
    const float* dWhh1 = (const float*)in[15];
    const float* db1   = (const float*)in[16];
    const float* fcW   = (const float*)in[17];
    const float* fcb   = (const float*)in[18];
    float* out = (float*)d_out;

    static int smem_set = 0;
    if (!smem_set) {
        cudaFuncSetAttribute(rnn_kernel, cudaFuncAttributeMaxDynamicSharedMemorySize,
                             W_SMEM_BYTES);
        smem_set = 1;
    }

    reset_kernel<<<1250, 256>>>(out);
    gather_kernel<<<2048, 256>>>(embE, src, NCOLS_E, 0);
    gather_kernel<<<2032, 256>>>(embD, trg, NCOLS_D, 1);
    repack_kernel<<<512, 256>>>(eWhh0, dWhh0, eWih1, eWhh1, dWih1, dWhh1);

    gemm_kernel<<<dim3(NCOLS_E / 64, 2048 / 64), 256>>>(eWih0, 2048, EE, 0, eb0,
                                                        nullptr, nullptr, nullptr);
    gemm_kernel<<<dim3(NCOLS_D / 64, 2048 / 64), 256>>>(dWih0, 2048, EE, 1, db0,
                                                        nullptr, nullptr, nullptr);
    rnn_kernel<<<RNN_CTAS, RNN_THREADS, W_SMEM_BYTES>>>(eb1, db1);
    gemm_kernel<<<dim3(NCOLS_D / 64, (VV + 63) / 64), 256>>>(fcW, VV, HH, 2, fcb,
                                                             src, vs, out);
}

// round 8
// speedup vs baseline: 1.0983x; 1.0983x over previous
#include <cuda_runtime.h>
#include <cuda_bf16.h>
#include <cstdint>

typedef unsigned long long ull;

#define TT   128
#define BB   64
#define HH   512
#define EE   256
#define VV   5000
#define NSTEP 255          /* 128 enc + 127 dec */
#define NCOLS_E 8192       /* 128*64 */
#define NCOLS_D 8128       /* 127*64 */
#define RNN_CTAS 128
/* smem floats: w0 8192 | w1 16384 | red0 1024 | red1 1024 */
#define RED0_OFF 24576
#define RED1_OFF 25600
#define W_SMEM_FLOATS 26624
#define W_SMEM_BYTES  (W_SMEM_FLOATS * 4)

/* ---------------- device scratch (static, no allocation) ---------------- */
__device__ float g_xe[NCOLS_E][EE];
__device__ float g_xd[NCOLS_D][EE];
__device__ float g_pre_e[TT][HH][BB][4];
__device__ float g_pre_d[TT - 1][HH][BB][4];
__device__ float g_w0e[HH][HH][4];
__device__ float g_w0d[HH][HH][4];
__device__ float g_w1e[HH][2 * HH][4];
__device__ float g_w1d[HH][2 * HH][4];
__device__ float g_h0[2][HH][BB];
__device__ float g_h1[2][HH][BB];
__device__ float g_hist[NCOLS_D][HH];
__device__ unsigned g_count;
__device__ unsigned g_phase;

/* ---------------- f32x2 helpers ---------------- */
__device__ __forceinline__ void fma2(ull& acc, ull a, ull b) {
    asm("fma.rn.f32x2 %0, %1, %2, %0;" : "+l"(acc) : "l"(a), "l"(b));
}
__device__ __forceinline__ ull add2(ull a, ull b) {
    ull r; asm("add.rn.f32x2 %0, %1, %2;" : "=l"(r) : "l"(a), "l"(b));
    return r;
}
__device__ __forceinline__ ull splat2(float x) {
    ull r; unsigned u = __float_as_uint(x);
    asm("mov.b64 %0, {%1, %1};" : "=l"(r) : "r"(u));
    return r;
}
__device__ __forceinline__ float2 unpack2(ull v) {
    unsigned lo, hi;
    asm("mov.b64 {%0, %1}, %2;" : "=r"(lo), "=r"(hi) : "l"(v));
    float2 f; f.x = __uint_as_float(lo); f.y = __uint_as_float(hi);
    return f;
}
__device__ __forceinline__ float sigf(float x) { return 1.0f / (1.0f + __expf(-x)); }

/* ---------------- setup: out zero, h init, flags, BOTH embedding gathers ---------------- */
__global__ void setup_kernel(float* __restrict__ out,
                             const float* __restrict__ embE, const int* __restrict__ src,
                             const float* __restrict__ embD, const int* __restrict__ trg) {
    int i = blockIdx.x * blockDim.x + threadIdx.x;
    if (i < NCOLS_E * 64) {
        int col = i >> 6, e4 = i & 63;
        ((float4*)&g_xe[0][0])[(size_t)col * 64 + e4] =
            ((const float4*)embE)[(size_t)src[col] * 64 + e4];
    } else if (i < NCOLS_E * 64 + NCOLS_D * 64) {
        int j2 = i - NCOLS_E * 64;
        int col = j2 >> 6, e4 = j2 & 63;
        ((float4*)&g_xd[0][0])[(size_t)col * 64 + e4] =
            ((const float4*)embD)[(size_t)trg[col] * 64 + e4];
    }
    if (i < BB * VV) out[i] = 0.0f;
    if (i < HH * BB) {
        (&g_h0[0][0][0])[i] = 0.0f;
        (&g_h1[0][0][0])[i] = 0.0f;
    }
    if (i == 0) { g_count = 0u; g_phase = 0u; }
}

/* ---------------- weight repack ---------------- */
__global__ void repack_kernel(const float* __restrict__ eWhh0, const float* __restrict__ dWhh0,
                              const float* __restrict__ eWih1, const float* __restrict__ eWhh1,
                              const float* __restrict__ dWih1, const float* __restrict__ dWhh1) {
    int stride = gridDim.x * blockDim.x;
    int idx = blockIdx.x * blockDim.x + threadIdx.x;
    for (int i = idx; i < HH * HH; i += stride) {
        int u = i / HH, k = i % HH;
        #pragma unroll
        for (int g = 0; g < 4; g++) {
            g_w0e[u][k][g] = eWhh0[(size_t)(g * HH + u) * HH + k];
            g_w0d[u][k][g] = dWhh0[(size_t)(g * HH + u) * HH + k];
        }
    }
    for (int i = idx; i < HH * 2 * HH; i += stride) {
        int u = i / (2 * HH), k = i % (2 * HH);
        #pragma unroll
        for (int g = 0; g < 4; g++) {
            float ve, vd;
            if (k < HH) { ve = eWih1[(size_t)(g * HH + u) * HH + k];
                          vd = dWih1[(size_t)(g * HH + u) * HH + k]; }
            else        { ve = eWhh1[(size_t)(g * HH + u) * HH + (k - HH)];
                          vd = dWhh1[(size_t)(g * HH + u) * HH + (k - HH)]; }
            g_w1e[u][k][g] = ve;
            g_w1d[u][k][g] = vd;
        }
    }
}

/* ---------------- generic 64x64 tiled fp32 GEMM, C = A(MxK) * B(NxK)^T ----------------
   mode 0: merged pre enc+dec (blockIdx.x < 128 -> enc, else dec)
   mode 2: fc epilogue -> d_out (+bias, vocab_sim mask)                        */
__global__ void __launch_bounds__(256) gemm_kernel(
    const float* __restrict__ Aenc, const float* __restrict__ Adec,
    int M, int K, int mode,
    const float* __restrict__ biasE, const float* __restrict__ biasD,
    const int* __restrict__ src, const float* __restrict__ vs,
    float* __restrict__ outp) {
    __shared__ float As[32][64];
    __shared__ float Bs[32][64];

    int tid = threadIdx.x;
    int r = (tid & 15) << 2;
    int c = (tid >> 4) << 2;
    int m0 = blockIdx.y * 64;

    const float* A;
    const float* bias;
    const float* B;
    float* dst = nullptr;
    int n0;
    bool dec = false;
    if (mode == 0) {
        dec = (blockIdx.x >= NCOLS_E / 64);
        A    = dec ? Adec : Aenc;
        bias = dec ? biasD : biasE;
        B    = dec ? &g_xd[0][0] : &g_xe[0][0];
        dst  = dec ? &g_pre_d[0][0][0][0] : &g_pre_e[0][0][0][0];
        n0   = (dec ? (int)blockIdx.x - NCOLS_E / 64 : (int)blockIdx.x) * 64;
    } else {
        A = Aenc; bias = biasE; B = &g_hist[0][0];
        n0 = blockIdx.x * 64;
    }

    ull acc[4][2];
    #pragma unroll
    for (int i = 0; i < 4; i++) { acc[i][0] = 0ull; acc[i][1] = 0ull; }

    for (int kt = 0; kt < K; kt += 32) {
        #pragma unroll
        for (int rep = 0; rep < 2; rep++) {
            int f = tid + rep * 256;
            int m = f >> 3;
            int k4 = (f & 7) << 2;
            int gm = m0 + m;
            float4 va = make_float4(0.f, 0.f, 0.f, 0.f);
            if (gm < M) va = *(const float4*)&A[(size_t)gm * K + kt + k4];
            As[k4 + 0][m] = va.x; As[k4 + 1][m] = va.y;
            As[k4 + 2][m] = va.z; As[k4 + 3][m] = va.w;
            float4 vb = *(const float4*)&B[(size_t)(n0 + m) * K + kt + k4];
            Bs[k4 + 0][m] = vb.x; Bs[k4 + 1][m] = vb.y;
            Bs[k4 + 2][m] = vb.z; Bs[k4 + 3][m] = vb.w;
        }
        __syncthreads();
        #pragma unroll
        for (int k = 0; k < 32; k++) {
            float4 av = *(const float4*)&As[k][r];
            float4 bv = *(const float4*)&Bs[k][c];
            ull b01 = ((const ull*)&bv)[0];
            ull b23 = ((const ull*)&bv)[1];
            ull a0 = splat2(av.x), a1 = splat2(av.y), a2 = splat2(av.z), a3 = splat2(av.w);
            fma2(acc[0][0], a0, b01); fma2(acc[0][1], a0, b23);
            fma2(acc[1][0], a1, b01); fma2(acc[1][1], a1, b23);
            fma2(acc[2][0], a2, b01); fma2(acc[2][1], a2, b23);
            fma2(acc[3][0], a3, b01); fma2(acc[3][1], a3, b23);
        }
        __syncthreads();
    }

    #pragma unroll
    for (int i = 0; i < 4; i++) {
        int m = m0 + r + i;
        if (m >= M) continue;
        float bval = bias[m];
        float2 v01 = unpack2(acc[i][0]);
        float2 v23 = unpack2(acc[i][1]);
        float vals[4] = { v01.x + bval, v01.y + bval, v23.x + bval, v23.y + bval };
        #pragma unroll
        for (int j = 0; j < 4; j++) {
            int n = n0 + c + j;
            if (mode == 2) {
                int s0 = src[n], s1 = src[n + 64];
                float sim = fminf(vs[(size_t)s0 * VV + m], vs[(size_t)s1 * VV + m]);
                float md = fminf(sim, 20.0f);
                float mult = (m == 3 || m == 4 || m == VV - 1) ? 1.0f
                                                               : (md * md - 20.0f * md + 1.0f);
                outp[(size_t)(n + 64) * VV + m] = vals[j] * mult;
            } else {
                int t = n >> 6, b = n & 63;
                int uu = m & 511, g = m >> 9;
                dst[(((size_t)t * HH + uu) * BB + b) * 4 + g] = vals[j];
            }
        }
    }
}

/* ---------------- grid barrier (sense by monotone phase) ---------------- */
__device__ __forceinline__ void grid_barrier(unsigned nctas, unsigned& local_phase) {
    __syncthreads();
    if (threadIdx.x == 0) {
        unsigned target = local_phase + 1u;
        __threadfence();
        unsigned old = atomicAdd(&g_count, 1u);
        if (old == nctas - 1u) {
            g_count = 0u;
            __threadfence();
            atomicExch(&g_phase, target);
        } else {
            if (*(volatile unsigned*)&g_phase < target) {
                while (*(volatile unsigned*)&g_phase < target) { __nanosleep(32); }
            }
            __threadfence();
        }
    }
    local_phase++;
    __syncthreads();
}

/* ---------------- software-pipelined GEMV over cnt k values (depth 16) ---------------- */
__device__ __forceinline__ void gemv_pass(const float* __restrict__ hbase,
                                          const ulonglong2* __restrict__ wbase,
                                          int cnt,
                                          ull& aif0, ull& ago0, ull& aif1, ull& ago1) {
    float2 bufA[16], bufB[16];
    #pragma unroll
    for (int i = 0; i < 16; i++)
        bufA[i] = *(const float2*)(hbase + (size_t)i * BB);

    #pragma unroll 1
    for (int k = 0; k < cnt; k += 32) {
        #pragma unroll
        for (int i = 0; i < 16; i++)
            bufB[i] = *(const float2*)(hbase + (size_t)(k + 16 + i) * BB);
        #pragma unroll
        for (int i = 0; i < 16; i++) {
            ulonglong2 w = wbase[k + i];
            ull ha = splat2(bufA[i].x), hb = splat2(bufA[i].y);
            fma2(aif0, ha, w.x); fma2(ago0, ha, w.y);
            fma2(aif1, hb, w.x); fma2(ago1, hb, w.y);
        }
        int kn = (k + 32 < cnt) ? (k + 32) : 0;   /* harmless wrap prefetch */
        #pragma unroll
        for (int i = 0; i < 16; i++)
            bufA[i] = *(const float2*)(hbase + (size_t)(kn + i) * BB);
        #pragma unroll
        for (int i = 0; i < 16; i++) {
            ulonglong2 w = wbase[k + 16 + i];
            ull ha = splat2(bufB[i].x), hb = splat2(bufB[i].y);
            fma2(aif0, ha, w.x); fma2(ago0, ha, w.y);
            fma2(aif1, hb, w.x); fma2(ago1, hb, w.y);
        }
    }
}

/* ---------------- persistent LSTM recurrence: 256 thr, 2 warps/SMSP ----------------
   warps 0-3 (group A): own unit usub, lanes = batch pairs; do epilogues.
   warps 4-7 (group B): second half of k work.
   Layer 0: A takes k[0,256), B takes k[256,512)        -> reduce in red0.
   Layer 1: A does h0new pass, B does h1old pass        -> reduce in red1. */
__global__ void __launch_bounds__(256, 1) rnn_kernel(const float* __restrict__ eb1,
                                                     const float* __restrict__ db1) {
    extern __shared__ float s_w[];
    const int tid  = threadIdx.x;
    const int lane = tid & 31;
    const int warp = tid >> 5;
    const int grp  = warp >> 2;
    const int usub = warp & 3;
    const int u = blockIdx.x * 4 + usub;
    const int b0 = lane * 2;
    const int slot = tid & 127;
    const unsigned nctas = gridDim.x;
    unsigned phase = 0;

    ull* red0 = (ull*)&s_w[RED0_OFF];
    ull* red1 = (ull*)&s_w[RED1_OFF];

    float2 c0 = make_float2(0.f, 0.f);
    float2 c1 = make_float2(0.f, 0.f);

    float be[4], bd[4];
    #pragma unroll
    for (int g = 0; g < 4; g++) { be[g] = eb1[g * HH + u]; bd[g] = db1[g * HH + u]; }

    const ulonglong2* w0s = (const ulonglong2*)&s_w[usub * 2048];          /* [512]  */
    const ulonglong2* w1s = (const ulonglong2*)&s_w[8192 + usub * 4096];   /* [1024] */

    for (int t = 0; t < NSTEP; t++) {
        const bool enc = (t < TT);

        if (t == 0 || t == TT) {
            const float4* src0 = (const float4*)(enc ? &g_w0e[blockIdx.x * 4][0][0]
                                                     : &g_w0d[blockIdx.x * 4][0][0]);
            const float4* src1 = (const float4*)(enc ? &g_w1e[blockIdx.x * 4][0][0]
                                                     : &g_w1d[blockIdx.x * 4][0][0]);
            float4* d0 = (float4*)s_w;
            float4* d1 = (float4*)(s_w + 8192);
            for (int i = tid; i < 2048; i += 256) d0[i] = src0[i];
            for (int i = tid; i < 4096; i += 256) d1[i] = src1[i];
            __syncthreads();
        }

        /* hoisted pre-activation loads (DRAM-cold; overlap with the GEMV below) */
        float4 p0 = make_float4(0.f, 0.f, 0.f, 0.f);
        float4 p1 = p0;
        if (grp == 0) {
            const float4* pre4 = enc ? (const float4*)&g_pre_e[t][u][0][0]
                                     : (const float4*)&g_pre_d[t - TT][u][0][0];
            p0 = pre4[b0];
            p1 = pre4[b0 + 1];
        }

        /* ---- layer 0: gates = pre[t] + Whh0 @ h0old, k split A/B ---- */
        const float* h0old = &g_h0[t & 1][0][0] + b0;
        ull aif0 = 0ull, ago0 = 0ull, aif1 = 0ull, ago1 = 0ull;
        if (grp == 0) {
            gemv_pass(h0old, w0s, 256, aif0, ago0, aif1, ago1);
        } else {
            gemv_pass(h0old + 256 * BB, w0s + 256, 256, aif0, ago0, aif1, ago1);
            red0[slot * 4 + 0] = aif0; red0[slot * 4 + 1] = ago0;
            red0[slot * 4 + 2] = aif1; red0[slot * 4 + 3] = ago1;
        }
        __syncthreads();
        if (grp == 0) {
            aif0 = add2(aif0, red0[slot * 4 + 0]);
            ago0 = add2(ago0, red0[slot * 4 + 1]);
            aif1 = add2(aif1, red0[slot * 4 + 2]);
            ago1 = add2(ago1, red0[slot * 4 + 3]);
            float2 if0 = unpack2(aif0), go0 = unpack2(ago0);
            float2 if1 = unpack2(aif1), go1 = unpack2(ago1);
            float zi0 = if0.x + p0.x, zf0 = if0.y + p0.y;
            float zg0 = go0.x + p0.z, zo0 = go0.y + p0.w;
            float zi1 = if1.x + p1.x, zf1 = if1.y + p1.y;
            float zg1 = go1.x + p1.z, zo1 = go1.y + p1.w;
            c0.x = sigf(zf0) * c0.x + sigf(zi0) * tanhf(zg0);
            c0.y = sigf(zf1) * c0.y + sigf(zi1) * tanhf(zg1);
            float2 h0n;
            h0n.x = sigf(zo0) * tanhf(c0.x);
            h0n.y = sigf(zo1) * tanhf(c0.y);
            *(float2*)(&g_h0[(t + 1) & 1][0][0] + (size_t)u * BB + b0) = h0n;
        }

        grid_barrier(nctas, phase);

        /* ---- layer 1: A does Wih1@h0new, B does Whh1@h1old ---- */
        ull bif0 = 0ull, bgo0 = 0ull, bif1 = 0ull, bgo1 = 0ull;
        if (grp == 0) {
            const float* h0new = &g_h0[(t + 1) & 1][0][0] + b0;
            gemv_pass(h0new, w1s, 512, bif0, bgo0, bif1, bgo1);
        } else {
            const float* h1old = &g_h1[t & 1][0][0] + b0;
            gemv_pass(h1old, w1s + HH, 512, bif0, bgo0, bif1, bgo1);
            red1[slot * 4 + 0] = bif0; red1[slot * 4 + 1] = bgo0;
            red1[slot * 4 + 2] = bif1; red1[slot * 4 + 3] = bgo1;
        }
        __syncthreads();
        if (grp == 0) {
            bif0 = add2(bif0, red1[slot * 4 + 0]);
            bgo0 = add2(bgo0, red1[slot * 4 + 1]);
            bif1 = add2(bif1, red1[slot * 4 + 2]);
            bgo1 = add2(bgo1, red1[slot * 4 + 3]);
            float bi = enc ? be[0] : bd[0];
            float bf = enc ? be[1] : bd[1];
            float bg = enc ? be[2] : bd[2];
            float bo = enc ? be[3] : bd[3];
            float2 if0 = unpack2(bif0), go0 = unpack2(bgo0);
            float2 if1 = unpack2(bif1), go1 = unpack2(bgo1);
            float zi0 = if0.x + bi, zf0 = if0.y + bf;
            float zg0 = go0.x + bg, zo0 = go0.y + bo;
            float zi1 = if1.x + bi, zf1 = if1.y + bf;
            float zg1 = go1.x + bg, zo1 = go1.y + bo;
            c1.x = sigf(zf0) * c1.x + sigf(zi0) * tanhf(zg0);
            c1.y = sigf(zf1) * c1.y + sigf(zi1) * tanhf(zg1);
            float2 h1n;
            h1n.x = sigf(zo0) * tanhf(c1.x);
            h1n.y = sigf(zo1) * tanhf(c1.y);
            *(float2*)(&g_h1[(t + 1) & 1][0][0] + (size_t)u * BB + b0) = h1n;
            if (!enc) {
                int col = (t - TT) * BB + b0;
                g_hist[col][u] = h1n.x;
                g_hist[col + 1][u] = h1n.y;
            }
        }
        /* layer-1(t) writes are protected by the grid barrier inside step t+1 */
    }
}

/* ---------------- launch ---------------- */
extern "C" void kernel_launch(void* const* d_in, const int* in_sizes, int n_in,
                              void* d_out, int out_size) {
    const void* in[32];
    int j = 0;
    for (int k = 0; k < n_in && j < 32; k++) {
        if (in_sizes[k] == 1) continue;       /* skip scalar src_lens/trg_lens */
        in[j++] = d_in[k];
    }
    const int*   src   = (const int*)in[0];
    const int*   trg   = (const int*)in[1];
    const float* vs    = (const float*)in[2];
    const float* embE  = (const float*)in[3];
    const float* embD  = (const float*)in[4];
    const float* eWih0 = (const float*)in[5];
    const float* eWhh0 = (const float*)in[6];
    const float* eb0   = (const float*)in[7];
    const float* eWih1 = (const float*)in[8];
    const float* eWhh1 = (const float*)in[9];
    const float* eb1   = (const float*)in[10];
    const float* dWih0 = (const float*)in[11];
    const float* dWhh0 = (const float*)in[12];
    const float* db0   = (const float*)in[13];
    const float* dWih1 = (const float*)in[14];
    const float* dWhh1 = (const float*)in[15];
    const float* db1   = (const float*)in[16];
    const float* fcW   = (const float*)in[17];
    const float* fcb   = (const float*)in[18];
    float* out = (float*)d_out;

    static int smem_set = 0;
    if (!smem_set) {
        cudaFuncSetAttribute(rnn_kernel, cudaFuncAttributeMaxDynamicSharedMemorySize,
                             W_SMEM_BYTES);
        smem_set = 1;
    }

    /* 1: setup (out zero + h init + flags + both gathers) */
    setup_kernel<<<4080, 256>>>(out, embE, src, embD, trg);
    /* 2: weight repack */
    repack_kernel<<<512, 256>>>(eWhh0, dWhh0, eWih1, eWhh1, dWih1, dWhh1);
    /* 3: merged layer-0 input preactivations (enc blocks 0-127, dec blocks 128-254) */
    gemm_kernel<<<dim3(NCOLS_E / 64 + NCOLS_D / 64, 2048 / 64), 256>>>(
        eWih0, dWih0, 2048, EE, 0, eb0, db0, nullptr, nullptr, nullptr);
    /* 4: serial recurrence (lands on ncu's capture slot) */
    rnn_kernel<<<RNN_CTAS, 256, W_SMEM_BYTES>>>(eb1, db1);
    /* 5: vocab projection + similarity mask */
    gemm_kernel<<<dim3(NCOLS_D / 64, (VV + 63) / 64), 256>>>(
        fcW, nullptr, VV, HH, 2, fcb, nullptr, src, vs, out);
}

// round 9
// speedup vs baseline: 1.2630x; 1.1499x over previous
#include <cuda_runtime.h>
#include <cuda_bf16.h>
#include <cstdint>

typedef unsigned long long ull;

#define TT   128
#define BB   64
#define HH   512
#define EE   256
#define VV   5000
#define NSTEP 255          /* 128 enc + 127 dec */
#define NCOLS_E 8192       /* 128*64 */
#define NCOLS_D 8128       /* 127*64 */
#define RNN_CTAS 128
/* smem floats: w0 8192 | w1 16384 | red0 8192 (4096 ull) | red1 8192 */
#define RED0_F  24576
#define RED1_F  32768
#define W_SMEM_FLOATS 40960
#define W_SMEM_BYTES  (W_SMEM_FLOATS * 4)   /* 163840 */

/* ---------------- device scratch (static, no allocation) ---------------- */
__device__ float g_xe[NCOLS_E][EE];
__device__ float g_xd[NCOLS_D][EE];
__device__ float g_pre_e[TT][HH][BB][4];
__device__ float g_pre_d[TT - 1][HH][BB][4];
__device__ float g_w0e[HH][HH][4];
__device__ float g_w0d[HH][HH][4];
__device__ float g_w1e[HH][2 * HH][4];
__device__ float g_w1d[HH][2 * HH][4];
__device__ float g_h0[2][HH][BB];
__device__ float g_h1[2][HH][BB];
__device__ float g_hist[NCOLS_D][HH];
__device__ unsigned g_count;
__device__ unsigned g_phase;

/* ---------------- f32x2 helpers ---------------- */
__device__ __forceinline__ void fma2(ull& acc, ull a, ull b) {
    asm("fma.rn.f32x2 %0, %1, %2, %0;" : "+l"(acc) : "l"(a), "l"(b));
}
__device__ __forceinline__ ull add2(ull a, ull b) {
    ull r; asm("add.rn.f32x2 %0, %1, %2;" : "=l"(r) : "l"(a), "l"(b));
    return r;
}
__device__ __forceinline__ ull splat2(float x) {
    ull r; unsigned u = __float_as_uint(x);
    asm("mov.b64 %0, {%1, %1};" : "=l"(r) : "r"(u));
    return r;
}
__device__ __forceinline__ float2 unpack2(ull v) {
    unsigned lo, hi;
    asm("mov.b64 {%0, %1}, %2;" : "=r"(lo), "=r"(hi) : "l"(v));
    float2 f; f.x = __uint_as_float(lo); f.y = __uint_as_float(hi);
    return f;
}
__device__ __forceinline__ float sigf(float x) { return 1.0f / (1.0f + __expf(-x)); }

/* ---------------- setup: out zero, h init, flags, BOTH embedding gathers ---------------- */
__global__ void setup_kernel(float* __restrict__ out,
                             const float* __restrict__ embE, const int* __restrict__ src,
                             const float* __restrict__ embD, const int* __restrict__ trg) {
    int i = blockIdx.x * blockDim.x + threadIdx.x;
    if (i < NCOLS_E * 64) {
        int col = i >> 6, e4 = i & 63;
        ((float4*)&g_xe[0][0])[(size_t)col * 64 + e4] =
            ((const float4*)embE)[(size_t)src[col] * 64 + e4];
    } else if (i < NCOLS_E * 64 + NCOLS_D * 64) {
        int j2 = i - NCOLS_E * 64;
        int col = j2 >> 6, e4 = j2 & 63;
        ((float4*)&g_xd[0][0])[(size_t)col * 64 + e4] =
            ((const float4*)embD)[(size_t)trg[col] * 64 + e4];
    }
    if (i < BB * VV) out[i] = 0.0f;
    if (i < HH * BB) {
        (&g_h0[0][0][0])[i] = 0.0f;
        (&g_h1[0][0][0])[i] = 0.0f;
    }
    if (i == 0) { g_count = 0u; g_phase = 0u; }
}

/* ---------------- weight repack ---------------- */
__global__ void repack_kernel(const float* __restrict__ eWhh0, const float* __restrict__ dWhh0,
                              const float* __restrict__ eWih1, const float* __restrict__ eWhh1,
                              const float* __restrict__ dWih1, const float* __restrict__ dWhh1) {
    int stride = gridDim.x * blockDim.x;
    int idx = blockIdx.x * blockDim.x + threadIdx.x;
    for (int i = idx; i < HH * HH; i += stride) {
        int u = i / HH, k = i % HH;
        #pragma unroll
        for (int g = 0; g < 4; g++) {
            g_w0e[u][k][g] = eWhh0[(size_t)(g * HH + u) * HH + k];
            g_w0d[u][k][g] = dWhh0[(size_t)(g * HH + u) * HH + k];
        }
    }
    for (int i = idx; i < HH * 2 * HH; i += stride) {
        int u = i / (2 * HH), k = i % (2 * HH);
        #pragma unroll
        for (int g = 0; g < 4; g++) {
            float ve, vd;
            if (k < HH) { ve = eWih1[(size_t)(g * HH + u) * HH + k];
                          vd = dWih1[(size_t)(g * HH + u) * HH + k]; }
            else        { ve = eWhh1[(size_t)(g * HH + u) * HH + (k - HH)];
                          vd = dWhh1[(size_t)(g * HH + u) * HH + (k - HH)]; }
            g_w1e[u][k][g] = ve;
            g_w1d[u][k][g] = vd;
        }
    }
}

/* ---------------- generic 64x64 tiled fp32 GEMM, C = A(MxK) * B(NxK)^T ---------------- */
__global__ void __launch_bounds__(256) gemm_kernel(
    const float* __restrict__ Aenc, const float* __restrict__ Adec,
    int M, int K, int mode,
    const float* __restrict__ biasE, const float* __restrict__ biasD,
    const int* __restrict__ src, const float* __restrict__ vs,
    float* __restrict__ outp) {
    __shared__ float As[32][64];
    __shared__ float Bs[32][64];

    int tid = threadIdx.x;
    int r = (tid & 15) << 2;
    int c = (tid >> 4) << 2;
    int m0 = blockIdx.y * 64;

    const float* A;
    const float* bias;
    const float* B;
    float* dst = nullptr;
    int n0;
    bool dec = false;
    if (mode == 0) {
        dec = (blockIdx.x >= NCOLS_E / 64);
        A    = dec ? Adec : Aenc;
        bias = dec ? biasD : biasE;
        B    = dec ? &g_xd[0][0] : &g_xe[0][0];
        dst  = dec ? &g_pre_d[0][0][0][0] : &g_pre_e[0][0][0][0];
        n0   = (dec ? (int)blockIdx.x - NCOLS_E / 64 : (int)blockIdx.x) * 64;
    } else {
        A = Aenc; bias = biasE; B = &g_hist[0][0];
        n0 = blockIdx.x * 64;
    }

    ull acc[4][2];
    #pragma unroll
    for (int i = 0; i < 4; i++) { acc[i][0] = 0ull; acc[i][1] = 0ull; }

    for (int kt = 0; kt < K; kt += 32) {
        #pragma unroll
        for (int rep = 0; rep < 2; rep++) {
            int f = tid + rep * 256;
            int m = f >> 3;
            int k4 = (f & 7) << 2;
            int gm = m0 + m;
            float4 va = make_float4(0.f, 0.f, 0.f, 0.f);
            if (gm < M) va = *(const float4*)&A[(size_t)gm * K + kt + k4];
            As[k4 + 0][m] = va.x; As[k4 + 1][m] = va.y;
            As[k4 + 2][m] = va.z; As[k4 + 3][m] = va.w;
            float4 vb = *(const float4*)&B[(size_t)(n0 + m) * K + kt + k4];
            Bs[k4 + 0][m] = vb.x; Bs[k4 + 1][m] = vb.y;
            Bs[k4 + 2][m] = vb.z; Bs[k4 + 3][m] = vb.w;
        }
        __syncthreads();
        #pragma unroll
        for (int k = 0; k < 32; k++) {
            float4 av = *(const float4*)&As[k][r];
            float4 bv = *(const float4*)&Bs[k][c];
            ull b01 = ((const ull*)&bv)[0];
            ull b23 = ((const ull*)&bv)[1];
            ull a0 = splat2(av.x), a1 = splat2(av.y), a2 = splat2(av.z), a3 = splat2(av.w);
            fma2(acc[0][0], a0, b01); fma2(acc[0][1], a0, b23);
            fma2(acc[1][0], a1, b01); fma2(acc[1][1], a1, b23);
            fma2(acc[2][0], a2, b01); fma2(acc[2][1], a2, b23);
            fma2(acc[3][0], a3, b01); fma2(acc[3][1], a3, b23);
        }
        __syncthreads();
    }

    #pragma unroll
    for (int i = 0; i < 4; i++) {
        int m = m0 + r + i;
        if (m >= M) continue;
        float bval = bias[m];
        float2 v01 = unpack2(acc[i][0]);
        float2 v23 = unpack2(acc[i][1]);
        float vals[4] = { v01.x + bval, v01.y + bval, v23.x + bval, v23.y + bval };
        #pragma unroll
        for (int j = 0; j < 4; j++) {
            int n = n0 + c + j;
            if (mode == 2) {
                int s0 = src[n], s1 = src[n + 64];
                float sim = fminf(vs[(size_t)s0 * VV + m], vs[(size_t)s1 * VV + m]);
                float md = fminf(sim, 20.0f);
                float mult = (m == 3 || m == 4 || m == VV - 1) ? 1.0f
                                                               : (md * md - 20.0f * md + 1.0f);
                outp[(size_t)(n + 64) * VV + m] = vals[j] * mult;
            } else {
                int t = n >> 6, b = n & 63;
                int uu = m & 511, g = m >> 9;
                dst[(((size_t)t * HH + uu) * BB + b) * 4 + g] = vals[j];
            }
        }
    }
}

/* ---------------- grid barrier (sense by monotone phase) ---------------- */
__device__ __forceinline__ void grid_barrier(unsigned nctas, unsigned& local_phase) {
    __syncthreads();
    if (threadIdx.x == 0) {
        unsigned target = local_phase + 1u;
        __threadfence();
        unsigned old = atomicAdd(&g_count, 1u);
        if (old == nctas - 1u) {
            g_count = 0u;
            __threadfence();
            atomicExch(&g_phase, target);
        } else {
            if (*(volatile unsigned*)&g_phase < target) {
                while (*(volatile unsigned*)&g_phase < target) { __nanosleep(32); }
            }
            __threadfence();
        }
    }
    local_phase++;
    __syncthreads();
}

/* ---------------- k-split GEMV: one warp, kcnt k values, ALL 4 units ----------------
   hbase: &h[kbase][b0]  (stride BB floats per k)
   wbase: &s_w[region + kbase*4] (u=0), ustride floats between units
   acc[u*4+0]={i,f}b0  +1={g,o}b0  +2={i,f}b1  +3={g,o}b1
   Each 8B h load feeds 16 fma2 (4x arithmetic intensity vs unit-split).      */
__device__ __forceinline__ void gemv4u(const float* __restrict__ hbase,
                                       const float* __restrict__ wbase,
                                       int ustride, int kcnt, ull* acc) {
    float2 bufA[8], bufB[8];
    #pragma unroll
    for (int i = 0; i < 8; i++)
        bufA[i] = *(const float2*)(hbase + (size_t)i * BB);

    #pragma unroll 1
    for (int k = 0; k < kcnt; k += 16) {
        #pragma unroll
        for (int i = 0; i < 8; i++)
            bufB[i] = *(const float2*)(hbase + (size_t)(k + 8 + i) * BB);
        #pragma unroll
        for (int i = 0; i < 8; i++) {
            ull ha = splat2(bufA[i].x), hb = splat2(bufA[i].y);
            #pragma unroll
            for (int u = 0; u < 4; u++) {
                ulonglong2 w = *(const ulonglong2*)(wbase + (size_t)u * ustride + (k + i) * 4);
                fma2(acc[u * 4 + 0], ha, w.x); fma2(acc[u * 4 + 1], ha, w.y);
                fma2(acc[u * 4 + 2], hb, w.x); fma2(acc[u * 4 + 3], hb, w.y);
            }
        }
        int kn = (k + 16 < kcnt) ? (k + 16) : 0;   /* harmless wrap prefetch */
        #pragma unroll
        for (int i = 0; i < 8; i++)
            bufA[i] = *(const float2*)(hbase + (size_t)(kn + i) * BB);
        #pragma unroll
        for (int i = 0; i < 8; i++) {
            ull ha = splat2(bufB[i].x), hb = splat2(bufB[i].y);
            #pragma unroll
            for (int u = 0; u < 4; u++) {
                ulonglong2 w = *(const ulonglong2*)(wbase + (size_t)u * ustride + (k + 8 + i) * 4);
                fma2(acc[u * 4 + 0], ha, w.x); fma2(acc[u * 4 + 1], ha, w.y);
                fma2(acc[u * 4 + 2], hb, w.x); fma2(acc[u * 4 + 3], hb, w.y);
            }
        }
    }
}

/* ---------------- persistent LSTM recurrence: 256 thr, k-split across warps ----------------
   GEMV role: warp w, lane l -> batch pair b0=2l; all 4 units per thread (16 accs).
     layer 0: warp w takes k in [64w, 64w+64) of Whh0 @ h0old
     layer 1: warps 0-3 take k in [128w,+128) of Wih1 @ h0new;
              warps 4-7 take k-512 in [128(w-4),+128) of Whh1 @ h1old
   Reduction: red[idx(16)][warp(8)][lane(32)] ull in smem; then
   epilogue role: thread t -> (u = t>>6, b = t&63), owns c-state, does activations. */
__global__ void __launch_bounds__(256, 1) rnn_kernel(const float* __restrict__ eb1,
                                                     const float* __restrict__ db1) {
    extern __shared__ float s_w[];
    const int tid  = threadIdx.x;
    const int lane = tid & 31;
    const int warp = tid >> 5;
    const int b0 = lane * 2;
    const int ublk = blockIdx.x * 4;
    const int eu = tid >> 6;            /* epilogue unit 0..3   */
    const int eb = tid & 63;            /* epilogue batch 0..63 */
    const int lsrc = eb >> 1;
    const int half = eb & 1;
    const unsigned nctas = gridDim.x;
    unsigned phase = 0;

    ull* red0 = (ull*)&s_w[RED0_F];
    ull* red1 = (ull*)&s_w[RED1_F];

    float c0s = 0.f, c1s = 0.f;
    float be[4], bd[4];
    #pragma unroll
    for (int g = 0; g < 4; g++) {
        be[g] = eb1[g * HH + ublk + eu];
        bd[g] = db1[g * HH + ublk + eu];
    }

    for (int t = 0; t < NSTEP; t++) {
        const bool enc = (t < TT);

        if (t == 0 || t == TT) {
            const float4* src0 = (const float4*)(enc ? &g_w0e[ublk][0][0] : &g_w0d[ublk][0][0]);
            const float4* src1 = (const float4*)(enc ? &g_w1e[ublk][0][0] : &g_w1d[ublk][0][0]);
            float4* d0 = (float4*)s_w;
            float4* d1 = (float4*)(s_w + 8192);
            for (int i = tid; i < 2048; i += 256) d0[i] = src0[i];
            for (int i = tid; i < 4096; i += 256) d1[i] = src1[i];
            __syncthreads();
        }

        /* hoisted pre-activation load for this thread's (u, b) */
        float4 p = enc ? *(const float4*)&g_pre_e[t][ublk + eu][eb][0]
                       : *(const float4*)&g_pre_d[t - TT][ublk + eu][eb][0];

        /* ---- layer 0 GEMV: k-split, all 4 units ---- */
        {
            ull acc[16];
            #pragma unroll
            for (int i = 0; i < 16; i++) acc[i] = 0ull;
            int kb = warp * 64;
            gemv4u(&g_h0[t & 1][kb][0] + b0, s_w + kb * 4, 2048, 64, acc);
            #pragma unroll
            for (int i = 0; i < 16; i++)
                red0[(i * 8 + warp) * 32 + lane] = acc[i];
        }
        __syncthreads();

        /* ---- layer 0 epilogue: all 256 threads, one (u,b) each ---- */
        {
            int iif = (eu * 4 + half * 2 + 0) * 8;
            int igo = (eu * 4 + half * 2 + 1) * 8;
            ull sif = red0[(iif + 0) * 32 + lsrc];
            ull sgo = red0[(igo + 0) * 32 + lsrc];
            #pragma unroll
            for (int w = 1; w < 8; w++) {
                sif = add2(sif, red0[(iif + w) * 32 + lsrc]);
                sgo = add2(sgo, red0[(igo + w) * 32 + lsrc]);
            }
            float2 vif = unpack2(sif), vgo = unpack2(sgo);
            float zi = vif.x + p.x, zf = vif.y + p.y;
            float zg = vgo.x + p.z, zo = vgo.y + p.w;
            c0s = sigf(zf) * c0s + sigf(zi) * tanhf(zg);
            float hn = sigf(zo) * tanhf(c0s);
            g_h0[(t + 1) & 1][ublk + eu][eb] = hn;
        }

        grid_barrier(nctas, phase);

        /* ---- layer 1 GEMV: warps 0-3 Wih1@h0new, warps 4-7 Whh1@h1old ---- */
        {
            ull acc[16];
            #pragma unroll
            for (int i = 0; i < 16; i++) acc[i] = 0ull;
            int kb = warp * 128;                       /* 0..896 in w1's k space */
            const float* hb = (warp < 4) ? (&g_h0[(t + 1) & 1][kb][0] + b0)
                                         : (&g_h1[t & 1][kb - 512][0] + b0);
            gemv4u(hb, s_w + 8192 + kb * 4, 4096, 128, acc);
            #pragma unroll
            for (int i = 0; i < 16; i++)
                red1[(i * 8 + warp) * 32 + lane] = acc[i];
        }
        __syncthreads();

        /* ---- layer 1 epilogue ---- */
        {
            int iif = (eu * 4 + half * 2 + 0) * 8;
            int igo = (eu * 4 + half * 2 + 1) * 8;
            ull sif = red1[(iif + 0) * 32 + lsrc];
            ull sgo = red1[(igo + 0) * 32 + lsrc];
            #pragma unroll
            for (int w = 1; w < 8; w++) {
                sif = add2(sif, red1[(iif + w) * 32 + lsrc]);
                sgo = add2(sgo, red1[(igo + w) * 32 + lsrc]);
            }
            float bi = enc ? be[0] : bd[0];
            float bf = enc ? be[1] : bd[1];
            float bg = enc ? be[2] : bd[2];
            float bo = enc ? be[3] : bd[3];
            float2 vif = unpack2(sif), vgo = unpack2(sgo);
            float zi = vif.x + bi, zf = vif.y + bf;
            float zg = vgo.x + bg, zo = vgo.y + bo;
            c1s = sigf(zf) * c1s + sigf(zi) * tanhf(zg);
            float hn = sigf(zo) * tanhf(c1s);
            g_h1[(t + 1) & 1][ublk + eu][eb] = hn;
            if (!enc) g_hist[(t - TT) * BB + eb][ublk + eu] = hn;
        }
        /* layer-1(t) writes are protected by the grid barrier inside step t+1 */
    }
}

/* ---------------- launch ---------------- */
extern "C" void kernel_launch(void* const* d_in, const int* in_sizes, int n_in,
                              void* d_out, int out_size) {
    const void* in[32];
    int j = 0;
    for (int k = 0; k < n_in && j < 32; k++) {
        if (in_sizes[k] == 1) continue;       /* skip scalar src_lens/trg_lens */
        in[j++] = d_in[k];
    }
    const int*   src   = (const int*)in[0];
    const int*   trg   = (const int*)in[1];
    const float* vs    = (const float*)in[2];
    const float* embE  = (const float*)in[3];
    const float* embD  = (const float*)in[4];
    const float* eWih0 = (const float*)in[5];
    const float* eWhh0 = (const float*)in[6];
    const float* eb0   = (const float*)in[7];
    const float* eWih1 = (const float*)in[8];
    const float* eWhh1 = (const float*)in[9];
    const float* eb1   = (const float*)in[10];
    const float* dWih0 = (const float*)in[11];
    const float* dWhh0 = (const float*)in[12];
    const float* db0   = (const float*)in[13];
    const float* dWih1 = (const float*)in[14];
    const float* dWhh1 = (const float*)in[15];
    const float* db1   = (const float*)in[16];
    const float* fcW   = (const float*)in[17];
    const float* fcb   = (const float*)in[18];
    float* out = (float*)d_out;

    static int smem_set = 0;
    if (!smem_set) {
        cudaFuncSetAttribute(rnn_kernel, cudaFuncAttributeMaxDynamicSharedMemorySize,
                             W_SMEM_BYTES);
        smem_set = 1;
    }

    /* 1: setup (out zero + h init + flags + both gathers) */
    setup_kernel<<<4080, 256>>>(out, embE, src, embD, trg);
    /* 2: weight repack */
    repack_kernel<<<512, 256>>>(eWhh0, dWhh0, eWih1, eWhh1, dWih1, dWhh1);
    /* 3: merged layer-0 input preactivations (enc blocks 0-127, dec blocks 128-254) */
    gemm_kernel<<<dim3(NCOLS_E / 64 + NCOLS_D / 64, 2048 / 64), 256>>>(
        eWih0, dWih0, 2048, EE, 0, eb0, db0, nullptr, nullptr, nullptr);
    /* 4: serial recurrence (lands on ncu's capture slot) */
    rnn_kernel<<<RNN_CTAS, 256, W_SMEM_BYTES>>>(eb1, db1);
    /* 5: vocab projection + similarity mask */
    gemm_kernel<<<dim3(NCOLS_D / 64, (VV + 63) / 64), 256>>>(
        fcW, nullptr, VV, HH, 2, fcb, nullptr, src, vs, out);
}

// round 10
// speedup vs baseline: 1.2900x; 1.0214x over previous
#include <cuda_runtime.h>
#include <cuda_bf16.h>
#include <cstdint>

typedef unsigned long long ull;

#define TT   128
#define BB   64
#define HH   512
#define EE   256
#define VV   5000
#define NSTEP 255          /* 128 enc + 127 dec */
#define NCOLS_E 8192       /* 128*64 */
#define NCOLS_D 8128       /* 127*64 */
#define RNN_CTAS 128
#define RNN_THREADS 512
/* smem floats: w0 8192 | w1 16384 | red0 16384 (8192 ull) | red1 16384 */
#define RED0_F  24576
#define RED1_F  40960
#define W_SMEM_FLOATS 57344
#define W_SMEM_BYTES  (W_SMEM_FLOATS * 4)   /* 229376 <= 232448 cap */

/* ---------------- device scratch (static, no allocation) ---------------- */
__device__ float g_xe[NCOLS_E][EE];
__device__ float g_xd[NCOLS_D][EE];
__device__ float g_pre_e[TT][HH][BB][4];
__device__ float g_pre_d[TT - 1][HH][BB][4];
__device__ float g_w0e[HH][HH][4];
__device__ float g_w0d[HH][HH][4];
__device__ float g_w1e[HH][2 * HH][4];
__device__ float g_w1d[HH][2 * HH][4];
__device__ float g_h0[2][HH][BB];
__device__ float g_h1[2][HH][BB];
__device__ float g_hist[NCOLS_D][HH];
__device__ unsigned g_count;
__device__ unsigned g_phase;

/* ---------------- f32x2 helpers ---------------- */
__device__ __forceinline__ void fma2(ull& acc, ull a, ull b) {
    asm("fma.rn.f32x2 %0, %1, %2, %0;" : "+l"(acc) : "l"(a), "l"(b));
}
__device__ __forceinline__ ull add2(ull a, ull b) {
    ull r; asm("add.rn.f32x2 %0, %1, %2;" : "=l"(r) : "l"(a), "l"(b));
    return r;
}
__device__ __forceinline__ ull splat2(float x) {
    ull r; unsigned u = __float_as_uint(x);
    asm("mov.b64 %0, {%1, %1};" : "=l"(r) : "r"(u));
    return r;
}
__device__ __forceinline__ float2 unpack2(ull v) {
    unsigned lo, hi;
    asm("mov.b64 {%0, %1}, %2;" : "=r"(lo), "=r"(hi) : "l"(v));
    float2 f; f.x = __uint_as_float(lo); f.y = __uint_as_float(hi);
    return f;
}
__device__ __forceinline__ float sigf(float x) { return 1.0f / (1.0f + __expf(-x)); }

/* ---------------- setup: out zero, h init, flags, BOTH embedding gathers ---------------- */
__global__ void setup_kernel(float* __restrict__ out,
                             const float* __restrict__ embE, const int* __restrict__ src,
                             const float* __restrict__ embD, const int* __restrict__ trg) {
    int i = blockIdx.x * blockDim.x + threadIdx.x;
    if (i < NCOLS_E * 64) {
        int col = i >> 6, e4 = i & 63;
        ((float4*)&g_xe[0][0])[(size_t)col * 64 + e4] =
            ((const float4*)embE)[(size_t)src[col] * 64 + e4];
    } else if (i < NCOLS_E * 64 + NCOLS_D * 64) {
        int j2 = i - NCOLS_E * 64;
        int col = j2 >> 6, e4 = j2 & 63;
        ((float4*)&g_xd[0][0])[(size_t)col * 64 + e4] =
            ((const float4*)embD)[(size_t)trg[col] * 64 + e4];
    }
    if (i < BB * VV) out[i] = 0.0f;
    if (i < HH * BB) {
        (&g_h0[0][0][0])[i] = 0.0f;
        (&g_h1[0][0][0])[i] = 0.0f;
    }
    if (i == 0) { g_count = 0u; g_phase = 0u; }
}

/* ---------------- weight repack ---------------- */
__global__ void repack_kernel(const float* __restrict__ eWhh0, const float* __restrict__ dWhh0,
                              const float* __restrict__ eWih1, const float* __restrict__ eWhh1,
                              const float* __restrict__ dWih1, const float* __restrict__ dWhh1) {
    int stride = gridDim.x * blockDim.x;
    int idx = blockIdx.x * blockDim.x + threadIdx.x;
    for (int i = idx; i < HH * HH; i += stride) {
        int u = i / HH, k = i % HH;
        #pragma unroll
        for (int g = 0; g < 4; g++) {
            g_w0e[u][k][g] = eWhh0[(size_t)(g * HH + u) * HH + k];
            g_w0d[u][k][g] = dWhh0[(size_t)(g * HH + u) * HH + k];
        }
    }
    for (int i = idx; i < HH * 2 * HH; i += stride) {
        int u = i / (2 * HH), k = i % (2 * HH);
        #pragma unroll
        for (int g = 0; g < 4; g++) {
            float ve, vd;
            if (k < HH) { ve = eWih1[(size_t)(g * HH + u) * HH + k];
                          vd = dWih1[(size_t)(g * HH + u) * HH + k]; }
            else        { ve = eWhh1[(size_t)(g * HH + u) * HH + (k - HH)];
                          vd = dWhh1[(size_t)(g * HH + u) * HH + (k - HH)]; }
            g_w1e[u][k][g] = ve;
            g_w1d[u][k][g] = vd;
        }
    }
}

/* ---------------- generic 64x64 tiled fp32 GEMM, C = A(MxK) * B(NxK)^T ---------------- */
__global__ void __launch_bounds__(256) gemm_kernel(
    const float* __restrict__ Aenc, const float* __restrict__ Adec,
    int M, int K, int mode,
    const float* __restrict__ biasE, const float* __restrict__ biasD,
    const int* __restrict__ src, const float* __restrict__ vs,
    float* __restrict__ outp) {
    __shared__ float As[32][64];
    __shared__ float Bs[32][64];

    int tid = threadIdx.x;
    int r = (tid & 15) << 2;
    int c = (tid >> 4) << 2;
    int m0 = blockIdx.y * 64;

    const float* A;
    const float* bias;
    const float* B;
    float* dst = nullptr;
    int n0;
    bool dec = false;
    if (mode == 0) {
        dec = (blockIdx.x >= NCOLS_E / 64);
        A    = dec ? Adec : Aenc;
        bias = dec ? biasD : biasE;
        B    = dec ? &g_xd[0][0] : &g_xe[0][0];
        dst  = dec ? &g_pre_d[0][0][0][0] : &g_pre_e[0][0][0][0];
        n0   = (dec ? (int)blockIdx.x - NCOLS_E / 64 : (int)blockIdx.x) * 64;
    } else {
        A = Aenc; bias = biasE; B = &g_hist[0][0];
        n0 = blockIdx.x * 64;
    }

    ull acc[4][2];
    #pragma unroll
    for (int i = 0; i < 4; i++) { acc[i][0] = 0ull; acc[i][1] = 0ull; }

    for (int kt = 0; kt < K; kt += 32) {
        #pragma unroll
        for (int rep = 0; rep < 2; rep++) {
            int f = tid + rep * 256;
            int m = f >> 3;
            int k4 = (f & 7) << 2;
            int gm = m0 + m;
            float4 va = make_float4(0.f, 0.f, 0.f, 0.f);
            if (gm < M) va = *(const float4*)&A[(size_t)gm * K + kt + k4];
            As[k4 + 0][m] = va.x; As[k4 + 1][m] = va.y;
            As[k4 + 2][m] = va.z; As[k4 + 3][m] = va.w;
            float4 vb = *(const float4*)&B[(size_t)(n0 + m) * K + kt + k4];
            Bs[k4 + 0][m] = vb.x; Bs[k4 + 1][m] = vb.y;
            Bs[k4 + 2][m] = vb.z; Bs[k4 + 3][m] = vb.w;
        }
        __syncthreads();
        #pragma unroll
        for (int k = 0; k < 32; k++) {
            float4 av = *(const float4*)&As[k][r];
            float4 bv = *(const float4*)&Bs[k][c];
            ull b01 = ((const ull*)&bv)[0];
            ull b23 = ((const ull*)&bv)[1];
            ull a0 = splat2(av.x), a1 = splat2(av.y), a2 = splat2(av.z), a3 = splat2(av.w);
            fma2(acc[0][0], a0, b01); fma2(acc[0][1], a0, b23);
            fma2(acc[1][0], a1, b01); fma2(acc[1][1], a1, b23);
            fma2(acc[2][0], a2, b01); fma2(acc[2][1], a2, b23);
            fma2(acc[3][0], a3, b01); fma2(acc[3][1], a3, b23);
        }
        __syncthreads();
    }

    #pragma unroll
    for (int i = 0; i < 4; i++) {
        int m = m0 + r + i;
        if (m >= M) continue;
        float bval = bias[m];
        float2 v01 = unpack2(acc[i][0]);
        float2 v23 = unpack2(acc[i][1]);
        float vals[4] = { v01.x + bval, v01.y + bval, v23.x + bval, v23.y + bval };
        #pragma unroll
        for (int j = 0; j < 4; j++) {
            int n = n0 + c + j;
            if (mode == 2) {
                int s0 = src[n], s1 = src[n + 64];
                float sim = fminf(vs[(size_t)s0 * VV + m], vs[(size_t)s1 * VV + m]);
                float md = fminf(sim, 20.0f);
                float mult = (m == 3 || m == 4 || m == VV - 1) ? 1.0f
                                                               : (md * md - 20.0f * md + 1.0f);
                outp[(size_t)(n + 64) * VV + m] = vals[j] * mult;
            } else {
                int t = n >> 6, b = n & 63;
                int uu = m & 511, g = m >> 9;
                dst[(((size_t)t * HH + uu) * BB + b) * 4 + g] = vals[j];
            }
        }
    }
}

/* ---------------- grid barrier (sense by monotone phase) ---------------- */
__device__ __forceinline__ void grid_barrier(unsigned nctas, unsigned& local_phase) {
    __syncthreads();
    if (threadIdx.x == 0) {
        unsigned target = local_phase + 1u;
        __threadfence();
        unsigned old = atomicAdd(&g_count, 1u);
        if (old == nctas - 1u) {
            g_count = 0u;
            __threadfence();
            atomicExch(&g_phase, target);
        } else {
            if (*(volatile unsigned*)&g_phase < target) {
                while (*(volatile unsigned*)&g_phase < target) { __nanosleep(32); }
            }
            __threadfence();
        }
    }
    local_phase++;
    __syncthreads();
}

/* ---------------- k-split GEMV: one warp, kcnt k values, ALL 4 units ----------------
   hbase: &h[kbase][b0]  (stride BB floats per k)
   wbase: &s_w[region + kbase*4] (u=0), ustride floats between units
   acc[u*4+0]={i,f}b0  +1={g,o}b0  +2={i,f}b1  +3={g,o}b1
   Depth-4 double buffering; 4 warps/SMSP supply the rest of the hiding.     */
__device__ __forceinline__ void gemv4u(const float* __restrict__ hbase,
                                       const float* __restrict__ wbase,
                                       int ustride, int kcnt, ull* acc) {
    float2 bufA[4], bufB[4];
    #pragma unroll
    for (int i = 0; i < 4; i++)
        bufA[i] = *(const float2*)(hbase + (size_t)i * BB);

    #pragma unroll 1
    for (int k = 0; k < kcnt; k += 8) {
        #pragma unroll
        for (int i = 0; i < 4; i++)
            bufB[i] = *(const float2*)(hbase + (size_t)(k + 4 + i) * BB);
        #pragma unroll
        for (int i = 0; i < 4; i++) {
            ull ha = splat2(bufA[i].x), hb = splat2(bufA[i].y);
            #pragma unroll
            for (int u = 0; u < 4; u++) {
                ulonglong2 w = *(const ulonglong2*)(wbase + (size_t)u * ustride + (k + i) * 4);
                fma2(acc[u * 4 + 0], ha, w.x); fma2(acc[u * 4 + 1], ha, w.y);
                fma2(acc[u * 4 + 2], hb, w.x); fma2(acc[u * 4 + 3], hb, w.y);
            }
        }
        int kn = (k + 8 < kcnt) ? (k + 8) : 0;   /* harmless wrap prefetch */
        #pragma unroll
        for (int i = 0; i < 4; i++)
            bufA[i] = *(const float2*)(hbase + (size_t)(kn + i) * BB);
        #pragma unroll
        for (int i = 0; i < 4; i++) {
            ull ha = splat2(bufB[i].x), hb = splat2(bufB[i].y);
            #pragma unroll
            for (int u = 0; u < 4; u++) {
                ulonglong2 w = *(const ulonglong2*)(wbase + (size_t)u * ustride + (k + 4 + i) * 4);
                fma2(acc[u * 4 + 0], ha, w.x); fma2(acc[u * 4 + 1], ha, w.y);
                fma2(acc[u * 4 + 2], hb, w.x); fma2(acc[u * 4 + 3], hb, w.y);
            }
        }
    }
}

/* ---------------- persistent LSTM recurrence: 512 thr, 4 warps/SMSP ----------------
   GEMV role: warp w (0..15), lane l -> batch pair b0=2l; all 4 units per thread.
     layer 0: warp w takes k in [32w, 32w+32) of Whh0 @ h0old
     layer 1: warps 0-7 take k in [64w,+64) of Wih1 @ h0new;
              warps 8-15 take k-512 in [64(w-8),+64) of Whh1 @ h1old
   Reduction: red[idx(16)][warp(16)][lane(32)] ull; epilogue on threads 0-255. */
__global__ void __launch_bounds__(RNN_THREADS, 1) rnn_kernel(const float* __restrict__ eb1,
                                                             const float* __restrict__ db1) {
    extern __shared__ float s_w[];
    const int tid  = threadIdx.x;
    const int lane = tid & 31;
    const int warp = tid >> 5;
    const int b0 = lane * 2;
    const int ublk = blockIdx.x * 4;
    const bool epi = (tid < 256);
    const int eu = (tid >> 6) & 3;      /* epilogue unit 0..3   */
    const int eb = tid & 63;            /* epilogue batch 0..63 */
    const int lsrc = eb >> 1;
    const int half = eb & 1;
    const unsigned nctas = gridDim.x;
    unsigned phase = 0;

    ull* red0 = (ull*)&s_w[RED0_F];
    ull* red1 = (ull*)&s_w[RED1_F];

    float c0s = 0.f, c1s = 0.f;
    float be[4], bd[4];
    #pragma unroll
    for (int g = 0; g < 4; g++) {
        be[g] = epi ? eb1[g * HH + ublk + eu] : 0.f;
        bd[g] = epi ? db1[g * HH + ublk + eu] : 0.f;
    }

    for (int t = 0; t < NSTEP; t++) {
        const bool enc = (t < TT);

        if (t == 0 || t == TT) {
            const float4* src0 = (const float4*)(enc ? &g_w0e[ublk][0][0] : &g_w0d[ublk][0][0]);
            const float4* src1 = (const float4*)(enc ? &g_w1e[ublk][0][0] : &g_w1d[ublk][0][0]);
            float4* d0 = (float4*)s_w;
            float4* d1 = (float4*)(s_w + 8192);
            for (int i = tid; i < 2048; i += RNN_THREADS) d0[i] = src0[i];
            for (int i = tid; i < 4096; i += RNN_THREADS) d1[i] = src1[i];
            __syncthreads();
        }

        /* hoisted pre-activation load for epilogue threads */
        float4 p = make_float4(0.f, 0.f, 0.f, 0.f);
        if (epi)
            p = enc ? *(const float4*)&g_pre_e[t][ublk + eu][eb][0]
                    : *(const float4*)&g_pre_d[t - TT][ublk + eu][eb][0];

        /* ---- layer 0 GEMV: k-split over 16 warps, all 4 units ---- */
        {
            ull acc[16];
            #pragma unroll
            for (int i = 0; i < 16; i++) acc[i] = 0ull;
            int kb = warp * 32;
            gemv4u(&g_h0[t & 1][kb][0] + b0, s_w + kb * 4, 2048, 32, acc);
            #pragma unroll
            for (int i = 0; i < 16; i++)
                red0[(i * 16 + warp) * 32 + lane] = acc[i];
        }
        __syncthreads();

        /* ---- layer 0 epilogue: threads 0-255, one (u,b) each ---- */
        if (epi) {
            int iif = (eu * 4 + half * 2 + 0) * 16;
            int igo = (eu * 4 + half * 2 + 1) * 16;
            ull sif = red0[(iif + 0) * 32 + lsrc];
            ull sgo = red0[(igo + 0) * 32 + lsrc];
            #pragma unroll
            for (int w = 1; w < 16; w++) {
                sif = add2(sif, red0[(iif + w) * 32 + lsrc]);
                sgo = add2(sgo, red0[(igo + w) * 32 + lsrc]);
            }
            float2 vif = unpack2(sif), vgo = unpack2(sgo);
            float zi = vif.x + p.x, zf = vif.y + p.y;
            float zg = vgo.x + p.z, zo = vgo.y + p.w;
            c0s = sigf(zf) * c0s + sigf(zi) * tanhf(zg);
            float hn = sigf(zo) * tanhf(c0s);
            g_h0[(t + 1) & 1][ublk + eu][eb] = hn;
        }

        grid_barrier(nctas, phase);

        /* ---- layer 1 GEMV: warps 0-7 Wih1@h0new, warps 8-15 Whh1@h1old ---- */
        {
            ull acc[16];
            #pragma unroll
            for (int i = 0; i < 16; i++) acc[i] = 0ull;
            int kb = warp * 64;                      /* 0..960 in w1's k space */
            const float* hb = (warp < 8) ? (&g_h0[(t + 1) & 1][kb][0] + b0)
                                         : (&g_h1[t & 1][kb - 512][0] + b0);
            gemv4u(hb, s_w + 8192 + kb * 4, 4096, 64, acc);
            #pragma unroll
            for (int i = 0; i < 16; i++)
                red1[(i * 16 + warp) * 32 + lane] = acc[i];
        }
        __syncthreads();

        /* ---- layer 1 epilogue ---- */
        if (epi) {
            int iif = (eu * 4 + half * 2 + 0) * 16;
            int igo = (eu * 4 + half * 2 + 1) * 16;
            ull sif = red1[(iif + 0) * 32 + lsrc];
            ull sgo = red1[(igo + 0) * 32 + lsrc];
            #pragma unroll
            for (int w = 1; w < 16; w++) {
                sif = add2(sif, red1[(iif + w) * 32 + lsrc]);
                sgo = add2(sgo, red1[(igo + w) * 32 + lsrc]);
            }
            float bi = enc ? be[0] : bd[0];
            float bf = enc ? be[1] : bd[1];
            float bg = enc ? be[2] : bd[2];
            float bo = enc ? be[3] : bd[3];
            float2 vif = unpack2(sif), vgo = unpack2(sgo);
            float zi = vif.x + bi, zf = vif.y + bf;
            float zg = vgo.x + bg, zo = vgo.y + bo;
            c1s = sigf(zf) * c1s + sigf(zi) * tanhf(zg);
            float hn = sigf(zo) * tanhf(c1s);
            g_h1[(t + 1) & 1][ublk + eu][eb] = hn;
            if (!enc) g_hist[(t - TT) * BB + eb][ublk + eu] = hn;
        }
        /* layer-1(t) writes are protected by the grid barrier inside step t+1;
           red0 rewrite next step is protected by grid_barrier's __syncthreads */
    }
}

/* ---------------- launch ---------------- */
extern "C" void kernel_launch(void* const* d_in, const int* in_sizes, int n_in,
                              void* d_out, int out_size) {
    const void* in[32];
    int j = 0;
    for (int k = 0; k < n_in && j < 32; k++) {
        if (in_sizes[k] == 1) continue;       /* skip scalar src_lens/trg_lens */
        in[j++] = d_in[k];
    }
    const int*   src   = (const int*)in[0];
    const int*   trg   = (const int*)in[1];
    const float* vs    = (const float*)in[2];
    const float* embE  = (const float*)in[3];
    const float* embD  = (const float*)in[4];
    const float* eWih0 = (const float*)in[5];
    const float* eWhh0 = (const float*)in[6];
    const float* eb0   = (const float*)in[7];
    const float* eWih1 = (const float*)in[8];
    const float* eWhh1 = (const float*)in[9];
    const float* eb1   = (const float*)in[10];
    const float* dWih0 = (const float*)in[11];
    const float* dWhh0 = (const float*)in[12];
    const float* db0   = (const float*)in[13];
    const float* dWih1 = (const float*)in[14];
    const float* dWhh1 = (const float*)in[15];
    const float* db1   = (const float*)in[16];
    const float* fcW   = (const float*)in[17];
    const float* fcb   = (const float*)in[18];
    float* out = (float*)d_out;

    static int smem_set = 0;
    if (!smem_set) {
        cudaFuncSetAttribute(rnn_kernel, cudaFuncAttributeMaxDynamicSharedMemorySize,
                             W_SMEM_BYTES);
        smem_set = 1;
    }

    /* 1: setup (out zero + h init + flags + both gathers) */
    setup_kernel<<<4080, 256>>>(out, embE, src, embD, trg);
    /* 2: weight repack */
    repack_kernel<<<512, 256>>>(eWhh0, dWhh0, eWih1, eWhh1, dWih1, dWhh1);
    /* 3: merged layer-0 input preactivations (enc blocks 0-127, dec blocks 128-254) */
    gemm_kernel<<<dim3(NCOLS_E / 64 + NCOLS_D / 64, 2048 / 64), 256>>>(
        eWih0, dWih0, 2048, EE, 0, eb0, db0, nullptr, nullptr, nullptr);
    /* 4: serial recurrence (lands on ncu's capture slot) */
    rnn_kernel<<<RNN_CTAS, RNN_THREADS, W_SMEM_BYTES>>>(eb1, db1);
    /* 5: vocab projection + similarity mask */
    gemm_kernel<<<dim3(NCOLS_D / 64, (VV + 63) / 64), 256>>>(
        fcW, nullptr, VV, HH, 2, fcb, nullptr, src, vs, out);
}